// round 1
// baseline (speedup 1.0000x reference)
#include <cuda_runtime.h>
#include <math.h>

namespace cfg {
constexpr int B  = 32;
constexpr int S  = 512;
constexpr int E  = 512;
constexpr int T  = 24;
constexpr int H  = 2;
constexpr int HD = E / H;          // 256
constexpr int BS = B * S;          // 16384
}

// ---------------- scratch (static device globals; no allocation) ------------
__device__ float g_qkv[(size_t)cfg::B * cfg::S * 3 * cfg::E];   // ~100 MB
__device__ float g_scores[(size_t)cfg::B * cfg::H * cfg::S * cfg::S]; // ~67 MB
__device__ float g_attn[(size_t)cfg::B * cfg::S * cfg::E];      // ~34 MB
__device__ float g_dec [(size_t)cfg::B * cfg::S * cfg::E];      // ~34 MB
__device__ float g_em  [(size_t)cfg::B * cfg::S * cfg::T];      // ~1.5 MB
__device__ float g_num [cfg::B];
__device__ float g_den [cfg::B];
__device__ float g_msum[cfg::B];

// ---------------- generic tiled SGEMM: C = alpha*A*op(B) + bias -------------
// A: M x K (lda).  TRANSB: B is N x K (ldb) -> C=A*B^T.  else B is K x N (ldb).
// Batched via blockIdx.z with (z/HH, z%HH) offset decomposition.
template<bool TRANSB, bool RELU>
__global__ __launch_bounds__(256, 2)
void sgemm(const float* __restrict__ A, const float* __restrict__ Bp,
           float* __restrict__ C, const float* __restrict__ bias,
           int M, int N, int K, int lda, int ldb, int ldc, float alpha,
           int HH, int sab, int sah, int sbb, int sbh, int scb, int sch)
{
    int z = blockIdx.z;
    A  += (size_t)(z / HH) * sab + (size_t)(z % HH) * sah;
    Bp += (size_t)(z / HH) * sbb + (size_t)(z % HH) * sbh;
    C  += (size_t)(z / HH) * scb + (size_t)(z % HH) * sch;

    __shared__ float As[8][128];
    __shared__ float Bs[8][128];

    const int tid = threadIdx.x;
    const int m0 = blockIdx.y * 128;
    const int n0 = blockIdx.x * 128;
    const int tx = tid & 15;    // 0..15 -> n microtile
    const int ty = tid >> 4;    // 0..15 -> m microtile

    float acc[8][8];
#pragma unroll
    for (int i = 0; i < 8; i++)
#pragma unroll
        for (int j = 0; j < 8; j++) acc[i][j] = 0.f;

    const int arow = tid >> 1;        // 0..127
    const int ak   = (tid & 1) * 4;   // 0 or 4

    for (int k0 = 0; k0 < K; k0 += 8) {
        // ---- load A tile (128 x 8), store transposed into As[k][m]
        float4 av = *(const float4*)(A + (size_t)(m0 + arow) * lda + k0 + ak);
        As[ak + 0][arow] = av.x;
        As[ak + 1][arow] = av.y;
        As[ak + 2][arow] = av.z;
        As[ak + 3][arow] = av.w;

        // ---- load B tile into Bs[k][n]
        if (TRANSB) {
            int n = n0 + arow;
            float4 bv = make_float4(0.f, 0.f, 0.f, 0.f);
            if (n < N)
                bv = *(const float4*)(Bp + (size_t)n * ldb + k0 + ak);
            Bs[ak + 0][arow] = bv.x;
            Bs[ak + 1][arow] = bv.y;
            Bs[ak + 2][arow] = bv.z;
            Bs[ak + 3][arow] = bv.w;
        } else {
            int kk = tid >> 5;             // 0..7
            int nn = (tid & 31) * 4;       // 0..124
            float4 bv = make_float4(0.f, 0.f, 0.f, 0.f);
            if (n0 + nn < N)
                bv = *(const float4*)(Bp + (size_t)(k0 + kk) * ldb + n0 + nn);
            *(float4*)&Bs[kk][nn] = bv;
        }
        __syncthreads();

#pragma unroll
        for (int k = 0; k < 8; k++) {
            float ra[8], rb[8];
            *(float4*)&ra[0] = *(const float4*)&As[k][ty * 8];
            *(float4*)&ra[4] = *(const float4*)&As[k][ty * 8 + 4];
            *(float4*)&rb[0] = *(const float4*)&Bs[k][tx * 8];
            *(float4*)&rb[4] = *(const float4*)&Bs[k][tx * 8 + 4];
#pragma unroll
            for (int i = 0; i < 8; i++)
#pragma unroll
                for (int j = 0; j < 8; j++)
                    acc[i][j] = fmaf(ra[i], rb[j], acc[i][j]);
        }
        __syncthreads();
    }

#pragma unroll
    for (int i = 0; i < 8; i++) {
        int m = m0 + ty * 8 + i;
#pragma unroll
        for (int j = 0; j < 8; j++) {
            int n = n0 + tx * 8 + j;
            if (n < N) {
                float v = acc[i][j] * alpha;
                if (bias) v += bias[n];
                if (RELU) v = fmaxf(v, 0.f);
                C[(size_t)m * ldc + n] = v;
            }
        }
    }
}

// ---------------- row softmax (in place), rows of length 512 ----------------
__global__ void softmax_rows(float* __restrict__ p, int rows, int n)
{
    int row = blockIdx.x * blockDim.y + threadIdx.y;
    if (row >= rows) return;
    float* d = p + (size_t)row * n;
    int lane = threadIdx.x;

    float m = -INFINITY;
    for (int i = lane; i < n; i += 32) m = fmaxf(m, d[i]);
#pragma unroll
    for (int o = 16; o > 0; o >>= 1) m = fmaxf(m, __shfl_xor_sync(0xffffffffu, m, o));

    float s = 0.f;
    for (int i = lane; i < n; i += 32) s += __expf(d[i] - m);
#pragma unroll
    for (int o = 16; o > 0; o >>= 1) s += __shfl_xor_sync(0xffffffffu, s, o);

    float inv = 1.f / s;
    for (int i = lane; i < n; i += 32) d[i] = __expf(d[i] - m) * inv;
}

// ---------------- CRF: normalizer + numerator (warp0), viterbi (warp1) ------
__global__ __launch_bounds__(64)
void crf_kernel(const float* __restrict__ em, const int* __restrict__ labels,
                const unsigned char* __restrict__ mask,
                const float* __restrict__ start_t, const float* __restrict__ end_t,
                const float* __restrict__ trans,
                float* __restrict__ out,          // crf path -> out[0 .. B*S)
                float* __restrict__ num, float* __restrict__ den,
                float* __restrict__ msum)
{
    using namespace cfg;
    const int b = blockIdx.x;
    const int warp = threadIdx.x >> 5;
    const int lane = threadIdx.x & 31;
    const int j = lane < T ? lane : T - 1;     // clamp for OOB-safe loads

    __shared__ unsigned char hist[S - 1][T];
    __shared__ unsigned char path[S];

    // per-thread column of transition matrix: tc[i] = trans[i][j]
    float tc[T];
#pragma unroll
    for (int i = 0; i < T; i++) tc[i] = trans[i * T + j];

    const float* emb = em + (size_t)b * S * T;

    if (warp == 0) {
        // ---------- forward algorithm (normalizer) ----------
        float sc = start_t[j] + emb[j];
        for (int s = 1; s < S; s++) {
            float v[T];
#pragma unroll
            for (int i = 0; i < T; i++)
                v[i] = __shfl_sync(0xffffffffu, sc, i) + tc[i];
            float m = v[0];
#pragma unroll
            for (int i = 1; i < T; i++) m = fmaxf(m, v[i]);
            float sum = 0.f;
#pragma unroll
            for (int i = 0; i < T; i++) sum += __expf(v[i] - m);
            float nxt = m + __logf(sum) + emb[s * T + j];
            float mf = mask[b * S + s] ? 1.f : 0.f;
            sc = mf > 0.f ? nxt : sc;
        }
        float x = (lane < T) ? sc + end_t[j] : -INFINITY;
        float m = x;
#pragma unroll
        for (int o = 16; o > 0; o >>= 1) m = fmaxf(m, __shfl_xor_sync(0xffffffffu, m, o));
        float sum = (lane < T) ? __expf(x - m) : 0.f;
#pragma unroll
        for (int o = 16; o > 0; o >>= 1) sum += __shfl_xor_sync(0xffffffffu, sum, o);
        float d = m + __logf(sum);

        // ---------- numerator + mask sum ----------
        float part = 0.f, ms = 0.f;
        for (int s = lane; s < S; s += 32) ms += mask[b * S + s] ? 1.f : 0.f;
        for (int s = 1 + lane; s < S; s += 32) {
            int lp = labels[b * S + s - 1];
            int lc = labels[b * S + s];
            float mf = mask[b * S + s] ? 1.f : 0.f;
            part += (trans[lp * T + lc] + emb[s * T + lc]) * mf;
        }
#pragma unroll
        for (int o = 16; o > 0; o >>= 1) {
            part += __shfl_xor_sync(0xffffffffu, part, o);
            ms   += __shfl_xor_sync(0xffffffffu, ms, o);
        }
        if (lane == 0) {
            int se = (int)ms - 1;
            int l0 = labels[b * S + 0];
            int lt = labels[b * S + se];
            num[b]  = start_t[l0] + emb[l0] + part + end_t[lt];
            den[b]  = d;
            msum[b] = ms;
        }
    } else {
        // ---------- viterbi ----------
        float sc = start_t[j] + emb[j];
        for (int s = 1; s < S; s++) {
            float best = -INFINITY;
            int bi = 0;
#pragma unroll
            for (int i = 0; i < T; i++) {
                float vi = __shfl_sync(0xffffffffu, sc, i) + tc[i];
                if (vi > best) { best = vi; bi = i; }   // strict > -> first index on ties
            }
            if (lane < T) hist[s - 1][j] = (unsigned char)bi;
            sc = best + emb[s * T + j];
        }
        float x = (lane < T) ? sc + end_t[j] : -INFINITY;
        int idx = lane;
#pragma unroll
        for (int o = 16; o > 0; o >>= 1) {
            float ov = __shfl_down_sync(0xffffffffu, x, o);
            int   oi = __shfl_down_sync(0xffffffffu, idx, o);
            if (ov > x || (ov == x && oi < idx)) { x = ov; idx = oi; }
        }
        idx = __shfl_sync(0xffffffffu, idx, 0);
        __syncwarp();
        if (lane == 0) {
            int cur = idx;
            path[S - 1] = (unsigned char)cur;
            for (int s = S - 1; s >= 1; s--) {
                cur = hist[s - 1][cur];
                path[s - 1] = (unsigned char)cur;
            }
        }
        __syncwarp();
        for (int s = lane; s < S; s += 32)
            out[b * S + s] = (float)path[s];
    }
}

// ---------------- final scalar: -llh ----------------------------------------
__global__ void llh_kernel(const float* __restrict__ num, const float* __restrict__ den,
                           const float* __restrict__ msum, float* __restrict__ out)
{
    using namespace cfg;
    int lane = threadIdx.x;
    float v = (lane < B) ? num[lane] - den[lane] : 0.f;
    float m = (lane < B) ? msum[lane] : 0.f;
#pragma unroll
    for (int o = 16; o > 0; o >>= 1) {
        v += __shfl_xor_sync(0xffffffffu, v, o);
        m += __shfl_xor_sync(0xffffffffu, m, o);
    }
    if (lane == 0) out[3 * BS] = -(v / m);
}

// ---------------- seg head: log_softmax(dec @ ent_w^T + ent_b) --------------
__global__ __launch_bounds__(256)
void seg_kernel(const float* __restrict__ dec, const float* __restrict__ ent_w,
                const float* __restrict__ ent_b, float* __restrict__ out)
{
    using namespace cfg;
    int warp = threadIdx.x >> 5;
    int lane = threadIdx.x & 31;
    int row = blockIdx.x * 8 + warp;       // B*S rows
    if (row >= BS) return;
    const float* d = dec + (size_t)row * E;

    float a0 = 0.f, a1 = 0.f;
    for (int k = lane * 4; k < E; k += 128) {
        float4 dv = *(const float4*)(d + k);
        float4 w0 = *(const float4*)(ent_w + k);
        float4 w1 = *(const float4*)(ent_w + E + k);
        a0 += dv.x * w0.x + dv.y * w0.y + dv.z * w0.z + dv.w * w0.w;
        a1 += dv.x * w1.x + dv.y * w1.y + dv.z * w1.z + dv.w * w1.w;
    }
#pragma unroll
    for (int o = 16; o > 0; o >>= 1) {
        a0 += __shfl_xor_sync(0xffffffffu, a0, o);
        a1 += __shfl_xor_sync(0xffffffffu, a1, o);
    }
    if (lane == 0) {
        float z0 = a0 + ent_b[0];
        float z1 = a1 + ent_b[1];
        float m = fmaxf(z0, z1);
        float lse = m + __logf(__expf(z0 - m) + __expf(z1 - m));
        out[BS + (size_t)row * 2 + 0] = z0 - lse;
        out[BS + (size_t)row * 2 + 1] = z1 - lse;
    }
}

// ---------------- host launch ------------------------------------------------
extern "C" void kernel_launch(void* const* d_in, const int* in_sizes, int n_in,
                              void* d_out, int out_size)
{
    using namespace cfg;
    const float* x       = (const float*)d_in[0];
    const int*   labels  = (const int*)d_in[1];
    const unsigned char* mask = (const unsigned char*)d_in[2];
    const float* Win     = (const float*)d_in[3];
    const float* bin     = (const float*)d_in[4];
    const float* Wout    = (const float*)d_in[5];
    const float* bout    = (const float*)d_in[6];
    const float* crf_w   = (const float*)d_in[7];
    const float* crf_b   = (const float*)d_in[8];
    const float* start_t = (const float*)d_in[9];
    const float* end_t   = (const float*)d_in[10];
    const float* trans   = (const float*)d_in[11];
    const float* ent_w   = (const float*)d_in[12];
    const float* ent_b   = (const float*)d_in[13];
    float* out = (float*)d_out;

    float *qkv, *scores, *attn, *dec, *em, *num, *den, *msum;
    cudaGetSymbolAddress((void**)&qkv,    g_qkv);
    cudaGetSymbolAddress((void**)&scores, g_scores);
    cudaGetSymbolAddress((void**)&attn,   g_attn);
    cudaGetSymbolAddress((void**)&dec,    g_dec);
    cudaGetSymbolAddress((void**)&em,     g_em);
    cudaGetSymbolAddress((void**)&num,    g_num);
    cudaGetSymbolAddress((void**)&den,    g_den);
    cudaGetSymbolAddress((void**)&msum,   g_msum);

    // 1) qkv = x @ Win^T + bin          (16384 x 1536 x 512)
    sgemm<true, false><<<dim3(12, 128, 1), 256>>>(
        x, Win, qkv, bin, BS, 3 * E, E, E, E, 3 * E, 1.f,
        1, 0, 0, 0, 0, 0, 0);

    // 2) scores[b,h] = Q K^T / 16       (batched 64: 512 x 512 x 256)
    sgemm<true, false><<<dim3(4, 4, 64), 256>>>(
        qkv, qkv + E, scores, nullptr, S, S, HD, 3 * E, 3 * E, S, 1.f / 16.f,
        H, S * 3 * E, HD, S * 3 * E, HD, H * S * S, S * S);

    // 3) softmax over k
    softmax_rows<<<(B * H * S) / 8, dim3(32, 8)>>>(scores, B * H * S, S);

    // 4) attn[b,:,h*hd+] = P @ V        (batched 64: 512 x 256 x 512)
    sgemm<false, false><<<dim3(2, 4, 64), 256>>>(
        scores, qkv + 2 * E, attn, nullptr, S, HD, S, S, 3 * E, E, 1.f,
        H, H * S * S, S * S, S * 3 * E, HD, S * E, HD);

    // 5) dec = relu(attn @ Wout^T + bout)   (16384 x 512 x 512)
    sgemm<true, true><<<dim3(4, 128, 1), 256>>>(
        attn, Wout, dec, bout, BS, E, E, E, E, E, 1.f,
        1, 0, 0, 0, 0, 0, 0);

    // 6) em = dec @ crf_w^T + crf_b    (16384 x 24 x 512)
    sgemm<true, false><<<dim3(1, 128, 1), 256>>>(
        dec, crf_w, em, crf_b, BS, T, E, E, E, T, 1.f,
        1, 0, 0, 0, 0, 0, 0);

    // 7) CRF: normalizer+numerator (warp0) and viterbi+path (warp1)
    crf_kernel<<<B, 64>>>(em, labels, mask, start_t, end_t, trans,
                          out, num, den, msum);

    // 8) scalar loss
    llh_kernel<<<1, 32>>>(num, den, msum, out);

    // 9) seg head
    seg_kernel<<<BS / 8, 256>>>(dec, ent_w, ent_b, out);
}

// round 2
// speedup vs baseline: 1.0237x; 1.0237x over previous
#include <cuda_runtime.h>
#include <math.h>

namespace cfg {
constexpr int B  = 32;
constexpr int S  = 512;
constexpr int E  = 512;
constexpr int T  = 24;
constexpr int H  = 2;
constexpr int HD = E / H;          // 256
constexpr int BS = B * S;          // 16384
}

// ---------------- scratch (static device globals; no allocation) ------------
__device__ float g_qkv[(size_t)cfg::B * cfg::S * 3 * cfg::E];
__device__ float g_scores[(size_t)cfg::B * cfg::H * cfg::S * cfg::S];
__device__ float g_attn[(size_t)cfg::B * cfg::S * cfg::E];
__device__ float g_dec [(size_t)cfg::B * cfg::S * cfg::E];
__device__ float g_em  [(size_t)cfg::B * cfg::S * cfg::T];
__device__ float g_num [cfg::B];
__device__ float g_den [cfg::B];
__device__ float g_msum[cfg::B];

// ---------------- double-buffered tiled SGEMM: C = alpha*A*op(B) + bias -----
// A: M x K (lda).  TRANSB: B is N x K (ldb) -> C=A*B^T.  else B is K x N (ldb).
// 128x128 tile, BK=16, 256 threads, 8x8 microtile, smem double buffer with
// register prefetch -> one __syncthreads per K-tile.
template<bool TRANSB, bool RELU>
__global__ __launch_bounds__(256, 2)
void sgemm(const float* __restrict__ A, const float* __restrict__ Bp,
           float* __restrict__ C, const float* __restrict__ bias,
           int M, int N, int K, int lda, int ldb, int ldc, float alpha,
           int HH, int sab, int sah, int sbb, int sbh, int scb, int sch)
{
    constexpr int BK = 16;
    int z = blockIdx.z;
    A  += (size_t)(z / HH) * sab + (size_t)(z % HH) * sah;
    Bp += (size_t)(z / HH) * sbb + (size_t)(z % HH) * sbh;
    C  += (size_t)(z / HH) * scb + (size_t)(z % HH) * sch;

    __shared__ float As[2][BK][128];
    __shared__ float Bs[2][BK][128];

    const int tid = threadIdx.x;
    const int m0 = blockIdx.y * 128;
    const int n0 = blockIdx.x * 128;
    const int tx = tid & 15;    // n microtile
    const int ty = tid >> 4;    // m microtile

    // A loader: row = tid>>1 (0..127), k base = (tid&1)*8 (two float4s)
    const int arow = tid >> 1;
    const int ak   = (tid & 1) * 8;
    // B non-trans loader: kk = tid>>4 (0..15), nn = (tid&15)*8
    const int bkk = tid >> 4;
    const int bnn = (tid & 15) * 8;

    float acc[8][8];
#pragma unroll
    for (int i = 0; i < 8; i++)
#pragma unroll
        for (int j = 0; j < 8; j++) acc[i][j] = 0.f;

    const int nt = K / BK;

    float4 pa0, pa1, pb0, pb1;

    // ---- prologue: load tile 0 into buffer 0
    {
        const float* Ap = A + (size_t)(m0 + arow) * lda + ak;
        pa0 = *(const float4*)(Ap);
        pa1 = *(const float4*)(Ap + 4);
        if (TRANSB) {
            int n = n0 + arow;
            pb0 = make_float4(0.f,0.f,0.f,0.f); pb1 = pb0;
            if (n < N) {
                const float* Bq = Bp + (size_t)n * ldb + ak;
                pb0 = *(const float4*)(Bq);
                pb1 = *(const float4*)(Bq + 4);
            }
        } else {
            pb0 = make_float4(0.f,0.f,0.f,0.f); pb1 = pb0;
            if (n0 + bnn < N) {
                const float* Bq = Bp + (size_t)bkk * ldb + n0 + bnn;
                pb0 = *(const float4*)(Bq);
                pb1 = *(const float4*)(Bq + 4);
            }
        }
        As[0][ak+0][arow]=pa0.x; As[0][ak+1][arow]=pa0.y;
        As[0][ak+2][arow]=pa0.z; As[0][ak+3][arow]=pa0.w;
        As[0][ak+4][arow]=pa1.x; As[0][ak+5][arow]=pa1.y;
        As[0][ak+6][arow]=pa1.z; As[0][ak+7][arow]=pa1.w;
        if (TRANSB) {
            Bs[0][ak+0][arow]=pb0.x; Bs[0][ak+1][arow]=pb0.y;
            Bs[0][ak+2][arow]=pb0.z; Bs[0][ak+3][arow]=pb0.w;
            Bs[0][ak+4][arow]=pb1.x; Bs[0][ak+5][arow]=pb1.y;
            Bs[0][ak+6][arow]=pb1.z; Bs[0][ak+7][arow]=pb1.w;
        } else {
            *(float4*)&Bs[0][bkk][bnn]     = pb0;
            *(float4*)&Bs[0][bkk][bnn + 4] = pb1;
        }
    }
    __syncthreads();

    for (int t = 0; t < nt; t++) {
        const int cur = t & 1;
        const int nxt = cur ^ 1;
        const bool more = (t + 1) < nt;

        // ---- prefetch tile t+1 (GMEM -> regs); overlaps with compute below
        if (more) {
            int k0 = (t + 1) * BK;
            const float* Ap = A + (size_t)(m0 + arow) * lda + k0 + ak;
            pa0 = *(const float4*)(Ap);
            pa1 = *(const float4*)(Ap + 4);
            if (TRANSB) {
                int n = n0 + arow;
                pb0 = make_float4(0.f,0.f,0.f,0.f); pb1 = pb0;
                if (n < N) {
                    const float* Bq = Bp + (size_t)n * ldb + k0 + ak;
                    pb0 = *(const float4*)(Bq);
                    pb1 = *(const float4*)(Bq + 4);
                }
            } else {
                pb0 = make_float4(0.f,0.f,0.f,0.f); pb1 = pb0;
                if (n0 + bnn < N) {
                    const float* Bq = Bp + (size_t)(k0 + bkk) * ldb + n0 + bnn;
                    pb0 = *(const float4*)(Bq);
                    pb1 = *(const float4*)(Bq + 4);
                }
            }
        }

        // ---- compute over current buffer
#pragma unroll
        for (int k = 0; k < BK; k++) {
            float ra[8], rb[8];
            *(float4*)&ra[0] = *(const float4*)&As[cur][k][ty * 8];
            *(float4*)&ra[4] = *(const float4*)&As[cur][k][ty * 8 + 4];
            *(float4*)&rb[0] = *(const float4*)&Bs[cur][k][tx * 8];
            *(float4*)&rb[4] = *(const float4*)&Bs[cur][k][tx * 8 + 4];
#pragma unroll
            for (int i = 0; i < 8; i++)
#pragma unroll
                for (int j = 0; j < 8; j++)
                    acc[i][j] = fmaf(ra[i], rb[j], acc[i][j]);
        }

        // ---- store prefetched tile into the other buffer (safe: that buffer
        // was last read in iteration t-1, protected by the barrier below)
        if (more) {
            As[nxt][ak+0][arow]=pa0.x; As[nxt][ak+1][arow]=pa0.y;
            As[nxt][ak+2][arow]=pa0.z; As[nxt][ak+3][arow]=pa0.w;
            As[nxt][ak+4][arow]=pa1.x; As[nxt][ak+5][arow]=pa1.y;
            As[nxt][ak+6][arow]=pa1.z; As[nxt][ak+7][arow]=pa1.w;
            if (TRANSB) {
                Bs[nxt][ak+0][arow]=pb0.x; Bs[nxt][ak+1][arow]=pb0.y;
                Bs[nxt][ak+2][arow]=pb0.z; Bs[nxt][ak+3][arow]=pb0.w;
                Bs[nxt][ak+4][arow]=pb1.x; Bs[nxt][ak+5][arow]=pb1.y;
                Bs[nxt][ak+6][arow]=pb1.z; Bs[nxt][ak+7][arow]=pb1.w;
            } else {
                *(float4*)&Bs[nxt][bkk][bnn]     = pb0;
                *(float4*)&Bs[nxt][bkk][bnn + 4] = pb1;
            }
            __syncthreads();
        }
    }

#pragma unroll
    for (int i = 0; i < 8; i++) {
        int m = m0 + ty * 8 + i;
#pragma unroll
        for (int j = 0; j < 8; j++) {
            int n = n0 + tx * 8 + j;
            if (n < N) {
                float v = acc[i][j] * alpha;
                if (bias) v += bias[n];
                if (RELU) v = fmaxf(v, 0.f);
                C[(size_t)m * ldc + n] = v;
            }
        }
    }
}

// ---------------- row softmax (in place), rows of length 512 ----------------
__global__ void softmax_rows(float* __restrict__ p, int rows, int n)
{
    int row = blockIdx.x * blockDim.y + threadIdx.y;
    if (row >= rows) return;
    float* d = p + (size_t)row * n;
    int lane = threadIdx.x;

    float m = -INFINITY;
    for (int i = lane; i < n; i += 32) m = fmaxf(m, d[i]);
#pragma unroll
    for (int o = 16; o > 0; o >>= 1) m = fmaxf(m, __shfl_xor_sync(0xffffffffu, m, o));

    float s = 0.f;
    for (int i = lane; i < n; i += 32) s += __expf(d[i] - m);
#pragma unroll
    for (int o = 16; o > 0; o >>= 1) s += __shfl_xor_sync(0xffffffffu, s, o);

    float inv = 1.f / s;
    for (int i = lane; i < n; i += 32) d[i] = __expf(d[i] - m) * inv;
}

// ---------------- CRF: normalizer + numerator (warp0), viterbi (warp1) ------
__global__ __launch_bounds__(64)
void crf_kernel(const float* __restrict__ em, const int* __restrict__ labels,
                const unsigned char* __restrict__ mask,
                const float* __restrict__ start_t, const float* __restrict__ end_t,
                const float* __restrict__ trans,
                float* __restrict__ out,
                float* __restrict__ num, float* __restrict__ den,
                float* __restrict__ msum)
{
    using namespace cfg;
    const int b = blockIdx.x;
    const int warp = threadIdx.x >> 5;
    const int lane = threadIdx.x & 31;
    const int j = lane < T ? lane : T - 1;

    __shared__ unsigned char hist[S - 1][T];
    __shared__ unsigned char path[S];

    float tc[T];
#pragma unroll
    for (int i = 0; i < T; i++) tc[i] = trans[i * T + j];

    const float* emb = em + (size_t)b * S * T;

    if (warp == 0) {
        float sc = start_t[j] + emb[j];
        for (int s = 1; s < S; s++) {
            float v[T];
#pragma unroll
            for (int i = 0; i < T; i++)
                v[i] = __shfl_sync(0xffffffffu, sc, i) + tc[i];
            float m = v[0];
#pragma unroll
            for (int i = 1; i < T; i++) m = fmaxf(m, v[i]);
            float sum = 0.f;
#pragma unroll
            for (int i = 0; i < T; i++) sum += __expf(v[i] - m);
            float nxt = m + __logf(sum) + emb[s * T + j];
            float mf = mask[b * S + s] ? 1.f : 0.f;
            sc = mf > 0.f ? nxt : sc;
        }
        float x = (lane < T) ? sc + end_t[j] : -INFINITY;
        float m = x;
#pragma unroll
        for (int o = 16; o > 0; o >>= 1) m = fmaxf(m, __shfl_xor_sync(0xffffffffu, m, o));
        float sum = (lane < T) ? __expf(x - m) : 0.f;
#pragma unroll
        for (int o = 16; o > 0; o >>= 1) sum += __shfl_xor_sync(0xffffffffu, sum, o);
        float d = m + __logf(sum);

        float part = 0.f, ms = 0.f;
        for (int s = lane; s < S; s += 32) ms += mask[b * S + s] ? 1.f : 0.f;
        for (int s = 1 + lane; s < S; s += 32) {
            int lp = labels[b * S + s - 1];
            int lc = labels[b * S + s];
            float mf = mask[b * S + s] ? 1.f : 0.f;
            part += (trans[lp * T + lc] + emb[s * T + lc]) * mf;
        }
#pragma unroll
        for (int o = 16; o > 0; o >>= 1) {
            part += __shfl_xor_sync(0xffffffffu, part, o);
            ms   += __shfl_xor_sync(0xffffffffu, ms, o);
        }
        if (lane == 0) {
            int se = (int)ms - 1;
            int l0 = labels[b * S + 0];
            int lt = labels[b * S + se];
            num[b]  = start_t[l0] + emb[l0] + part + end_t[lt];
            den[b]  = d;
            msum[b] = ms;
        }
    } else {
        float sc = start_t[j] + emb[j];
        for (int s = 1; s < S; s++) {
            float best = -INFINITY;
            int bi = 0;
#pragma unroll
            for (int i = 0; i < T; i++) {
                float vi = __shfl_sync(0xffffffffu, sc, i) + tc[i];
                if (vi > best) { best = vi; bi = i; }
            }
            if (lane < T) hist[s - 1][j] = (unsigned char)bi;
            sc = best + emb[s * T + j];
        }
        float x = (lane < T) ? sc + end_t[j] : -INFINITY;
        int idx = lane;
#pragma unroll
        for (int o = 16; o > 0; o >>= 1) {
            float ov = __shfl_down_sync(0xffffffffu, x, o);
            int   oi = __shfl_down_sync(0xffffffffu, idx, o);
            if (ov > x || (ov == x && oi < idx)) { x = ov; idx = oi; }
        }
        idx = __shfl_sync(0xffffffffu, idx, 0);
        __syncwarp();
        if (lane == 0) {
            int cur = idx;
            path[S - 1] = (unsigned char)cur;
            for (int s = S - 1; s >= 1; s--) {
                cur = hist[s - 1][cur];
                path[s - 1] = (unsigned char)cur;
            }
        }
        __syncwarp();
        for (int s = lane; s < S; s += 32)
            out[b * S + s] = (float)path[s];
    }
}

// ---------------- final scalar: -llh ----------------------------------------
__global__ void llh_kernel(const float* __restrict__ num, const float* __restrict__ den,
                           const float* __restrict__ msum, float* __restrict__ out)
{
    using namespace cfg;
    int lane = threadIdx.x;
    float v = (lane < B) ? num[lane] - den[lane] : 0.f;
    float m = (lane < B) ? msum[lane] : 0.f;
#pragma unroll
    for (int o = 16; o > 0; o >>= 1) {
        v += __shfl_xor_sync(0xffffffffu, v, o);
        m += __shfl_xor_sync(0xffffffffu, m, o);
    }
    if (lane == 0) out[3 * BS] = -(v / m);
}

// ---------------- seg head: log_softmax(dec @ ent_w^T + ent_b) --------------
__global__ __launch_bounds__(256)
void seg_kernel(const float* __restrict__ dec, const float* __restrict__ ent_w,
                const float* __restrict__ ent_b, float* __restrict__ out)
{
    using namespace cfg;
    int warp = threadIdx.x >> 5;
    int lane = threadIdx.x & 31;
    int row = blockIdx.x * 8 + warp;
    if (row >= BS) return;
    const float* d = dec + (size_t)row * E;

    float a0 = 0.f, a1 = 0.f;
    for (int k = lane * 4; k < E; k += 128) {
        float4 dv = *(const float4*)(d + k);
        float4 w0 = *(const float4*)(ent_w + k);
        float4 w1 = *(const float4*)(ent_w + E + k);
        a0 += dv.x * w0.x + dv.y * w0.y + dv.z * w0.z + dv.w * w0.w;
        a1 += dv.x * w1.x + dv.y * w1.y + dv.z * w1.z + dv.w * w1.w;
    }
#pragma unroll
    for (int o = 16; o > 0; o >>= 1) {
        a0 += __shfl_xor_sync(0xffffffffu, a0, o);
        a1 += __shfl_xor_sync(0xffffffffu, a1, o);
    }
    if (lane == 0) {
        float z0 = a0 + ent_b[0];
        float z1 = a1 + ent_b[1];
        float m = fmaxf(z0, z1);
        float lse = m + __logf(__expf(z0 - m) + __expf(z1 - m));
        out[BS + (size_t)row * 2 + 0] = z0 - lse;
        out[BS + (size_t)row * 2 + 1] = z1 - lse;
    }
}

// ---------------- host launch ------------------------------------------------
extern "C" void kernel_launch(void* const* d_in, const int* in_sizes, int n_in,
                              void* d_out, int out_size)
{
    using namespace cfg;
    const float* x       = (const float*)d_in[0];
    const int*   labels  = (const int*)d_in[1];
    const unsigned char* mask = (const unsigned char*)d_in[2];
    const float* Win     = (const float*)d_in[3];
    const float* bin     = (const float*)d_in[4];
    const float* Wout    = (const float*)d_in[5];
    const float* bout    = (const float*)d_in[6];
    const float* crf_w   = (const float*)d_in[7];
    const float* crf_b   = (const float*)d_in[8];
    const float* start_t = (const float*)d_in[9];
    const float* end_t   = (const float*)d_in[10];
    const float* trans   = (const float*)d_in[11];
    const float* ent_w   = (const float*)d_in[12];
    const float* ent_b   = (const float*)d_in[13];
    float* out = (float*)d_out;

    float *qkv, *scores, *attn, *dec, *em, *num, *den, *msum;
    cudaGetSymbolAddress((void**)&qkv,    g_qkv);
    cudaGetSymbolAddress((void**)&scores, g_scores);
    cudaGetSymbolAddress((void**)&attn,   g_attn);
    cudaGetSymbolAddress((void**)&dec,    g_dec);
    cudaGetSymbolAddress((void**)&em,     g_em);
    cudaGetSymbolAddress((void**)&num,    g_num);
    cudaGetSymbolAddress((void**)&den,    g_den);
    cudaGetSymbolAddress((void**)&msum,   g_msum);

    // 1) qkv = x @ Win^T + bin          (16384 x 1536 x 512)
    sgemm<true, false><<<dim3(12, 128, 1), 256>>>(
        x, Win, qkv, bin, BS, 3 * E, E, E, E, 3 * E, 1.f,
        1, 0, 0, 0, 0, 0, 0);

    // 2) scores[b,h] = Q K^T / 16       (batched 64: 512 x 512 x 256)
    sgemm<true, false><<<dim3(4, 4, 64), 256>>>(
        qkv, qkv + E, scores, nullptr, S, S, HD, 3 * E, 3 * E, S, 1.f / 16.f,
        H, S * 3 * E, HD, S * 3 * E, HD, H * S * S, S * S);

    // 3) softmax over k
    softmax_rows<<<(B * H * S) / 8, dim3(32, 8)>>>(scores, B * H * S, S);

    // 4) attn[b,:,h*hd+] = P @ V        (batched 64: 512 x 256 x 512)
    sgemm<false, false><<<dim3(2, 4, 64), 256>>>(
        scores, qkv + 2 * E, attn, nullptr, S, HD, S, S, 3 * E, E, 1.f,
        H, H * S * S, S * S, S * 3 * E, HD, S * E, HD);

    // 5) dec = relu(attn @ Wout^T + bout)   (16384 x 512 x 512)
    sgemm<true, true><<<dim3(4, 128, 1), 256>>>(
        attn, Wout, dec, bout, BS, E, E, E, E, E, 1.f,
        1, 0, 0, 0, 0, 0, 0);

    // 6) em = dec @ crf_w^T + crf_b    (16384 x 24 x 512)
    sgemm<true, false><<<dim3(1, 128, 1), 256>>>(
        dec, crf_w, em, crf_b, BS, T, E, E, E, T, 1.f,
        1, 0, 0, 0, 0, 0, 0);

    // 7) CRF
    crf_kernel<<<B, 64>>>(em, labels, mask, start_t, end_t, trans,
                          out, num, den, msum);

    // 8) scalar loss
    llh_kernel<<<1, 32>>>(num, den, msum, out);

    // 9) seg head
    seg_kernel<<<BS / 8, 256>>>(dec, ent_w, ent_b, out);
}

// round 3
// speedup vs baseline: 1.9942x; 1.9481x over previous
#include <cuda_runtime.h>
#include <math.h>

namespace cfg {
constexpr int B  = 32;
constexpr int S  = 512;
constexpr int E  = 512;
constexpr int T  = 24;
constexpr int H  = 2;
constexpr int HD = E / H;          // 256
constexpr int BS = B * S;          // 16384
}

// ---------------- scratch (static device globals; no allocation) ------------
__device__ float g_qkv[(size_t)cfg::B * cfg::S * 3 * cfg::E];
__device__ float g_scores[(size_t)cfg::B * cfg::H * cfg::S * cfg::S];
__device__ float g_attn[(size_t)cfg::B * cfg::S * cfg::E];
__device__ float g_dec [(size_t)cfg::B * cfg::S * cfg::E];
__device__ float g_em  [(size_t)cfg::B * cfg::S * cfg::T];
__device__ float g_num [cfg::B];
__device__ float g_den [cfg::B];
__device__ float g_msum[cfg::B];

// ---------------- helpers ----------------------------------------------------
__device__ __forceinline__ unsigned f2tf(float x) {
    unsigned u;
    asm("cvt.rna.tf32.f32 %0, %1;" : "=r"(u) : "f"(x));
    return u;
}

__device__ __forceinline__ void mma_tf32(float* d, const unsigned* a, const unsigned* b) {
    asm volatile(
        "mma.sync.aligned.m16n8k8.row.col.f32.tf32.tf32.f32 "
        "{%0,%1,%2,%3}, {%4,%5,%6,%7}, {%8,%9}, {%0,%1,%2,%3};"
        : "+f"(d[0]), "+f"(d[1]), "+f"(d[2]), "+f"(d[3])
        : "r"(a[0]), "r"(a[1]), "r"(a[2]), "r"(a[3]), "r"(b[0]), "r"(b[1]));
}

// ---------------- TF32 tensor-core GEMM: C = alpha*A*op(B) + bias -----------
// A: M x K (lda).  TRANSB: B is N x K (ldb) -> C=A*B^T.  else B is K x N (ldb).
// 128x128 tile, BK=16, 256 threads (8 warps, 2x4), warp tile 64x32,
// mma.sync.m16n8k8 tf32, fp32 accumulate, double-buffered SMEM.
// SMEM: As[m][k] stride 20 (conflict-free frags), Bs[k][n] stride 136.
template<bool TRANSB, bool RELU>
__global__ __launch_bounds__(256, 2)
void tgemm(const float* __restrict__ A, const float* __restrict__ Bp,
           float* __restrict__ C, const float* __restrict__ bias,
           int M, int N, int K, int lda, int ldb, int ldc, float alpha,
           int HH, int sab, int sah, int sbb, int sbh, int scb, int sch)
{
    constexpr int BK   = 16;
    constexpr int ASTR = 20;    // As row stride (floats)
    constexpr int BSTR = 136;   // Bs row stride (floats)

    int z = blockIdx.z;
    A  += (size_t)(z / HH) * sab + (size_t)(z % HH) * sah;
    Bp += (size_t)(z / HH) * sbb + (size_t)(z % HH) * sbh;
    C  += (size_t)(z / HH) * scb + (size_t)(z % HH) * sch;

    __shared__ unsigned As[2][128 * ASTR];
    __shared__ unsigned Bs[2][BK * BSTR];

    const int tid  = threadIdx.x;
    const int warp = tid >> 5;
    const int lane = tid & 31;
    const int qid  = lane >> 2;     // 0..7
    const int cid  = lane & 3;      // 0..3

    const int m0 = blockIdx.y * 128;
    const int n0 = blockIdx.x * 128;
    const int wm = (warp >> 2) * 64;   // warp m offset (0,64)
    const int wn = (warp & 3) * 32;    // warp n offset (0,32,64,96)

    // loaders
    const int arow = tid >> 1;          // 0..127
    const int ak   = (tid & 1) * 8;     // 0 or 8
    const int bkk  = tid >> 4;          // 0..15
    const int bnn  = (tid & 15) * 8;    // 0..120

    float acc[4][4][4];
#pragma unroll
    for (int i = 0; i < 4; i++)
#pragma unroll
        for (int j = 0; j < 4; j++)
#pragma unroll
            for (int r = 0; r < 4; r++) acc[i][j][r] = 0.f;

    const int nt = K / BK;
    float4 pa0, pa1, pb0, pb1;

    // ---- tile loader lambda-ish macros ----
#define LOAD_GMEM(k0)                                                          \
    {                                                                          \
        const float* Ap = A + (size_t)(m0 + arow) * lda + (k0) + ak;           \
        pa0 = *(const float4*)(Ap);                                            \
        pa1 = *(const float4*)(Ap + 4);                                        \
        if (TRANSB) {                                                          \
            int n = n0 + arow;                                                 \
            pb0 = make_float4(0.f,0.f,0.f,0.f); pb1 = pb0;                     \
            if (n < N) {                                                       \
                const float* Bq = Bp + (size_t)n * ldb + (k0) + ak;            \
                pb0 = *(const float4*)(Bq);                                    \
                pb1 = *(const float4*)(Bq + 4);                                \
            }                                                                  \
        } else {                                                               \
            pb0 = make_float4(0.f,0.f,0.f,0.f); pb1 = pb0;                     \
            if (n0 + bnn < N) {                                                \
                const float* Bq = Bp + (size_t)((k0) + bkk) * ldb + n0 + bnn;  \
                pb0 = *(const float4*)(Bq);                                    \
                pb1 = *(const float4*)(Bq + 4);                                \
            }                                                                  \
        }                                                                      \
    }

#define STORE_SMEM(buf)                                                        \
    {                                                                          \
        uint4 ua0 = make_uint4(f2tf(pa0.x), f2tf(pa0.y), f2tf(pa0.z), f2tf(pa0.w)); \
        uint4 ua1 = make_uint4(f2tf(pa1.x), f2tf(pa1.y), f2tf(pa1.z), f2tf(pa1.w)); \
        *(uint4*)&As[buf][arow * ASTR + ak]     = ua0;                         \
        *(uint4*)&As[buf][arow * ASTR + ak + 4] = ua1;                         \
        if (TRANSB) {                                                          \
            int n = arow;                                                      \
            Bs[buf][(ak+0)*BSTR + n] = f2tf(pb0.x);                            \
            Bs[buf][(ak+1)*BSTR + n] = f2tf(pb0.y);                            \
            Bs[buf][(ak+2)*BSTR + n] = f2tf(pb0.z);                            \
            Bs[buf][(ak+3)*BSTR + n] = f2tf(pb0.w);                            \
            Bs[buf][(ak+4)*BSTR + n] = f2tf(pb1.x);                            \
            Bs[buf][(ak+5)*BSTR + n] = f2tf(pb1.y);                            \
            Bs[buf][(ak+6)*BSTR + n] = f2tf(pb1.z);                            \
            Bs[buf][(ak+7)*BSTR + n] = f2tf(pb1.w);                            \
        } else {                                                               \
            uint4 ub0 = make_uint4(f2tf(pb0.x), f2tf(pb0.y), f2tf(pb0.z), f2tf(pb0.w)); \
            uint4 ub1 = make_uint4(f2tf(pb1.x), f2tf(pb1.y), f2tf(pb1.z), f2tf(pb1.w)); \
            *(uint4*)&Bs[buf][bkk * BSTR + bnn]     = ub0;                     \
            *(uint4*)&Bs[buf][bkk * BSTR + bnn + 4] = ub1;                     \
        }                                                                      \
    }

    LOAD_GMEM(0);
    STORE_SMEM(0);
    __syncthreads();

    for (int t = 0; t < nt; t++) {
        const int cur = t & 1;
        const int nxt = cur ^ 1;
        const bool more = (t + 1) < nt;

        if (more) LOAD_GMEM((t + 1) * BK);

        // ---- compute on current buffer: 2 k-steps of 8
        const unsigned* Ab = As[cur];
        const unsigned* Bb = Bs[cur];
#pragma unroll
        for (int ks = 0; ks < 2; ks++) {
            const int k0 = ks * 8;
            unsigned af[4][4], bf[4][2];
#pragma unroll
            for (int mt = 0; mt < 4; mt++) {
                const int rb = wm + mt * 16 + qid;
                af[mt][0] = Ab[(rb    ) * ASTR + k0 + cid];
                af[mt][1] = Ab[(rb + 8) * ASTR + k0 + cid];
                af[mt][2] = Ab[(rb    ) * ASTR + k0 + cid + 4];
                af[mt][3] = Ab[(rb + 8) * ASTR + k0 + cid + 4];
            }
#pragma unroll
            for (int ntl = 0; ntl < 4; ntl++) {
                const int nb = wn + ntl * 8 + qid;
                bf[ntl][0] = Bb[(k0 + cid    ) * BSTR + nb];
                bf[ntl][1] = Bb[(k0 + cid + 4) * BSTR + nb];
            }
#pragma unroll
            for (int mt = 0; mt < 4; mt++)
#pragma unroll
                for (int ntl = 0; ntl < 4; ntl++)
                    mma_tf32(acc[mt][ntl], af[mt], bf[ntl]);
        }

        if (more) {
            STORE_SMEM(nxt);
            __syncthreads();
        }
    }

    // ---- epilogue
#pragma unroll
    for (int mt = 0; mt < 4; mt++) {
        const int r0 = m0 + wm + mt * 16 + qid;
#pragma unroll
        for (int ntl = 0; ntl < 4; ntl++) {
            const int c0 = n0 + wn + ntl * 8 + cid * 2;
            float* d = acc[mt][ntl];
#pragma unroll
            for (int half = 0; half < 2; half++) {
                const int r = r0 + half * 8;
#pragma unroll
                for (int e = 0; e < 2; e++) {
                    const int n = c0 + e;
                    if (n < N) {
                        float v = d[half * 2 + e] * alpha;
                        if (bias) v += bias[n];
                        if (RELU) v = fmaxf(v, 0.f);
                        C[(size_t)r * ldc + n] = v;
                    }
                }
            }
        }
    }
#undef LOAD_GMEM
#undef STORE_SMEM
}

// ---------------- row softmax (in place), rows of length 512 ----------------
__global__ void softmax_rows(float* __restrict__ p, int rows, int n)
{
    int row = blockIdx.x * blockDim.y + threadIdx.y;
    if (row >= rows) return;
    float* d = p + (size_t)row * n;
    int lane = threadIdx.x;

    float m = -INFINITY;
    for (int i = lane; i < n; i += 32) m = fmaxf(m, d[i]);
#pragma unroll
    for (int o = 16; o > 0; o >>= 1) m = fmaxf(m, __shfl_xor_sync(0xffffffffu, m, o));

    float s = 0.f;
    for (int i = lane; i < n; i += 32) s += __expf(d[i] - m);
#pragma unroll
    for (int o = 16; o > 0; o >>= 1) s += __shfl_xor_sync(0xffffffffu, s, o);

    float inv = 1.f / s;
    for (int i = lane; i < n; i += 32) d[i] = __expf(d[i] - m) * inv;
}

// ---------------- CRF: normalizer + numerator (warp0), viterbi (warp1) ------
__global__ __launch_bounds__(64)
void crf_kernel(const float* __restrict__ em, const int* __restrict__ labels,
                const unsigned char* __restrict__ mask,
                const float* __restrict__ start_t, const float* __restrict__ end_t,
                const float* __restrict__ trans,
                float* __restrict__ out,
                float* __restrict__ num, float* __restrict__ den,
                float* __restrict__ msum)
{
    using namespace cfg;
    const int b = blockIdx.x;
    const int warp = threadIdx.x >> 5;
    const int lane = threadIdx.x & 31;
    const int j = lane < T ? lane : T - 1;

    __shared__ unsigned char hist[S - 1][T];
    __shared__ unsigned char path[S];

    float tc[T];
#pragma unroll
    for (int i = 0; i < T; i++) tc[i] = trans[i * T + j];

    const float* emb = em + (size_t)b * S * T;

    if (warp == 0) {
        float sc = start_t[j] + emb[j];
        for (int s = 1; s < S; s++) {
            float v[T];
#pragma unroll
            for (int i = 0; i < T; i++)
                v[i] = __shfl_sync(0xffffffffu, sc, i) + tc[i];
            float m = v[0];
#pragma unroll
            for (int i = 1; i < T; i++) m = fmaxf(m, v[i]);
            float sum = 0.f;
#pragma unroll
            for (int i = 0; i < T; i++) sum += __expf(v[i] - m);
            float nxt = m + __logf(sum) + emb[s * T + j];
            float mf = mask[b * S + s] ? 1.f : 0.f;
            sc = mf > 0.f ? nxt : sc;
        }
        float x = (lane < T) ? sc + end_t[j] : -INFINITY;
        float m = x;
#pragma unroll
        for (int o = 16; o > 0; o >>= 1) m = fmaxf(m, __shfl_xor_sync(0xffffffffu, m, o));
        float sum = (lane < T) ? __expf(x - m) : 0.f;
#pragma unroll
        for (int o = 16; o > 0; o >>= 1) sum += __shfl_xor_sync(0xffffffffu, sum, o);
        float d = m + __logf(sum);

        float part = 0.f, ms = 0.f;
        for (int s = lane; s < S; s += 32) ms += mask[b * S + s] ? 1.f : 0.f;
        for (int s = 1 + lane; s < S; s += 32) {
            int lp = labels[b * S + s - 1];
            int lc = labels[b * S + s];
            float mf = mask[b * S + s] ? 1.f : 0.f;
            part += (trans[lp * T + lc] + emb[s * T + lc]) * mf;
        }
#pragma unroll
        for (int o = 16; o > 0; o >>= 1) {
            part += __shfl_xor_sync(0xffffffffu, part, o);
            ms   += __shfl_xor_sync(0xffffffffu, ms, o);
        }
        if (lane == 0) {
            int se = (int)ms - 1;
            int l0 = labels[b * S + 0];
            int lt = labels[b * S + se];
            num[b]  = start_t[l0] + emb[l0] + part + end_t[lt];
            den[b]  = d;
            msum[b] = ms;
        }
    } else {
        float sc = start_t[j] + emb[j];
        for (int s = 1; s < S; s++) {
            float best = -INFINITY;
            int bi = 0;
#pragma unroll
            for (int i = 0; i < T; i++) {
                float vi = __shfl_sync(0xffffffffu, sc, i) + tc[i];
                if (vi > best) { best = vi; bi = i; }
            }
            if (lane < T) hist[s - 1][j] = (unsigned char)bi;
            sc = best + emb[s * T + j];
        }
        float x = (lane < T) ? sc + end_t[j] : -INFINITY;
        int idx = lane;
#pragma unroll
        for (int o = 16; o > 0; o >>= 1) {
            float ov = __shfl_down_sync(0xffffffffu, x, o);
            int   oi = __shfl_down_sync(0xffffffffu, idx, o);
            if (ov > x || (ov == x && oi < idx)) { x = ov; idx = oi; }
        }
        idx = __shfl_sync(0xffffffffu, idx, 0);
        __syncwarp();
        if (lane == 0) {
            int cur = idx;
            path[S - 1] = (unsigned char)cur;
            for (int s = S - 1; s >= 1; s--) {
                cur = hist[s - 1][cur];
                path[s - 1] = (unsigned char)cur;
            }
        }
        __syncwarp();
        for (int s = lane; s < S; s += 32)
            out[b * S + s] = (float)path[s];
    }
}

// ---------------- final scalar: -llh ----------------------------------------
__global__ void llh_kernel(const float* __restrict__ num, const float* __restrict__ den,
                           const float* __restrict__ msum, float* __restrict__ out)
{
    using namespace cfg;
    int lane = threadIdx.x;
    float v = (lane < B) ? num[lane] - den[lane] : 0.f;
    float m = (lane < B) ? msum[lane] : 0.f;
#pragma unroll
    for (int o = 16; o > 0; o >>= 1) {
        v += __shfl_xor_sync(0xffffffffu, v, o);
        m += __shfl_xor_sync(0xffffffffu, m, o);
    }
    if (lane == 0) out[3 * BS] = -(v / m);
}

// ---------------- seg head: log_softmax(dec @ ent_w^T + ent_b) --------------
__global__ __launch_bounds__(256)
void seg_kernel(const float* __restrict__ dec, const float* __restrict__ ent_w,
                const float* __restrict__ ent_b, float* __restrict__ out)
{
    using namespace cfg;
    int warp = threadIdx.x >> 5;
    int lane = threadIdx.x & 31;
    int row = blockIdx.x * 8 + warp;
    if (row >= BS) return;
    const float* d = dec + (size_t)row * E;

    float a0 = 0.f, a1 = 0.f;
    for (int k = lane * 4; k < E; k += 128) {
        float4 dv = *(const float4*)(d + k);
        float4 w0 = *(const float4*)(ent_w + k);
        float4 w1 = *(const float4*)(ent_w + E + k);
        a0 += dv.x * w0.x + dv.y * w0.y + dv.z * w0.z + dv.w * w0.w;
        a1 += dv.x * w1.x + dv.y * w1.y + dv.z * w1.z + dv.w * w1.w;
    }
#pragma unroll
    for (int o = 16; o > 0; o >>= 1) {
        a0 += __shfl_xor_sync(0xffffffffu, a0, o);
        a1 += __shfl_xor_sync(0xffffffffu, a1, o);
    }
    if (lane == 0) {
        float z0 = a0 + ent_b[0];
        float z1 = a1 + ent_b[1];
        float m = fmaxf(z0, z1);
        float lse = m + __logf(__expf(z0 - m) + __expf(z1 - m));
        out[BS + (size_t)row * 2 + 0] = z0 - lse;
        out[BS + (size_t)row * 2 + 1] = z1 - lse;
    }
}

// ---------------- host launch ------------------------------------------------
extern "C" void kernel_launch(void* const* d_in, const int* in_sizes, int n_in,
                              void* d_out, int out_size)
{
    using namespace cfg;
    const float* x       = (const float*)d_in[0];
    const int*   labels  = (const int*)d_in[1];
    const unsigned char* mask = (const unsigned char*)d_in[2];
    const float* Win     = (const float*)d_in[3];
    const float* bin     = (const float*)d_in[4];
    const float* Wout    = (const float*)d_in[5];
    const float* bout    = (const float*)d_in[6];
    const float* crf_w   = (const float*)d_in[7];
    const float* crf_b   = (const float*)d_in[8];
    const float* start_t = (const float*)d_in[9];
    const float* end_t   = (const float*)d_in[10];
    const float* trans   = (const float*)d_in[11];
    const float* ent_w   = (const float*)d_in[12];
    const float* ent_b   = (const float*)d_in[13];
    float* out = (float*)d_out;

    float *qkv, *scores, *attn, *dec, *em, *num, *den, *msum;
    cudaGetSymbolAddress((void**)&qkv,    g_qkv);
    cudaGetSymbolAddress((void**)&scores, g_scores);
    cudaGetSymbolAddress((void**)&attn,   g_attn);
    cudaGetSymbolAddress((void**)&dec,    g_dec);
    cudaGetSymbolAddress((void**)&em,     g_em);
    cudaGetSymbolAddress((void**)&num,    g_num);
    cudaGetSymbolAddress((void**)&den,    g_den);
    cudaGetSymbolAddress((void**)&msum,   g_msum);

    // 1) qkv = x @ Win^T + bin          (16384 x 1536 x 512)
    tgemm<true, false><<<dim3(12, 128, 1), 256>>>(
        x, Win, qkv, bin, BS, 3 * E, E, E, E, 3 * E, 1.f,
        1, 0, 0, 0, 0, 0, 0);

    // 2) scores[b,h] = Q K^T / 16       (batched 64: 512 x 512 x 256)
    tgemm<true, false><<<dim3(4, 4, 64), 256>>>(
        qkv, qkv + E, scores, nullptr, S, S, HD, 3 * E, 3 * E, S, 1.f / 16.f,
        H, S * 3 * E, HD, S * 3 * E, HD, H * S * S, S * S);

    // 3) softmax over k
    softmax_rows<<<(B * H * S) / 8, dim3(32, 8)>>>(scores, B * H * S, S);

    // 4) attn[b,:,h*hd+] = P @ V        (batched 64: 512 x 256 x 512)
    tgemm<false, false><<<dim3(2, 4, 64), 256>>>(
        scores, qkv + 2 * E, attn, nullptr, S, HD, S, S, 3 * E, E, 1.f,
        H, H * S * S, S * S, S * 3 * E, HD, S * E, HD);

    // 5) dec = relu(attn @ Wout^T + bout)   (16384 x 512 x 512)
    tgemm<true, true><<<dim3(4, 128, 1), 256>>>(
        attn, Wout, dec, bout, BS, E, E, E, E, E, 1.f,
        1, 0, 0, 0, 0, 0, 0);

    // 6) em = dec @ crf_w^T + crf_b    (16384 x 24 x 512)
    tgemm<true, false><<<dim3(1, 128, 1), 256>>>(
        dec, crf_w, em, crf_b, BS, T, E, E, E, T, 1.f,
        1, 0, 0, 0, 0, 0, 0);

    // 7) CRF
    crf_kernel<<<B, 64>>>(em, labels, mask, start_t, end_t, trans,
                          out, num, den, msum);

    // 8) scalar loss
    llh_kernel<<<1, 32>>>(num, den, msum, out);

    // 9) seg head
    seg_kernel<<<BS / 8, 256>>>(dec, ent_w, ent_b, out);
}

// round 6
// speedup vs baseline: 2.2735x; 1.1401x over previous
#include <cuda_runtime.h>
#include <math.h>

namespace cfg {
constexpr int B  = 32;
constexpr int S  = 512;
constexpr int E  = 512;
constexpr int T  = 24;
constexpr int H  = 2;
constexpr int HD = E / H;          // 256
constexpr int BS = B * S;          // 16384
}

// ---------------- scratch (static device globals; no allocation) ------------
__device__ float g_qkv[(size_t)cfg::B * cfg::S * 3 * cfg::E];
__device__ float g_scores[(size_t)cfg::B * cfg::H * cfg::S * cfg::S];
__device__ float g_attn[(size_t)cfg::B * cfg::S * cfg::E];
__device__ float g_dec [(size_t)cfg::B * cfg::S * cfg::E];
__device__ float g_em  [(size_t)cfg::B * cfg::S * cfg::T];
__device__ float g_num [cfg::B];
__device__ float g_den [cfg::B];
__device__ float g_msum[cfg::B];

// ---------------- helpers ----------------------------------------------------
__device__ __forceinline__ unsigned f2tf(unsigned rawf32) {
    unsigned u;
    asm("cvt.rna.tf32.f32 %0, %1;" : "=r"(u) : "f"(__uint_as_float(rawf32)));
    return u;
}

__device__ __forceinline__ void mma_tf32(float* d, const unsigned* a, const unsigned* b) {
    asm volatile(
        "mma.sync.aligned.m16n8k8.row.col.f32.tf32.tf32.f32 "
        "{%0,%1,%2,%3}, {%4,%5,%6,%7}, {%8,%9}, {%0,%1,%2,%3};"
        : "+f"(d[0]), "+f"(d[1]), "+f"(d[2]), "+f"(d[3])
        : "r"(a[0]), "r"(a[1]), "r"(a[2]), "r"(a[3]), "r"(b[0]), "r"(b[1]));
}

__device__ __forceinline__ void cp16(unsigned dst, const float* src, bool pred) {
    int sz = pred ? 16 : 0;
    asm volatile("cp.async.cg.shared.global [%0], [%1], 16, %2;"
                 :: "r"(dst), "l"(src), "r"(sz));
}
__device__ __forceinline__ void cp_commit() {
    asm volatile("cp.async.commit_group;");
}
template<int N0>
__device__ __forceinline__ void cp_wait() {
    asm volatile("cp.async.wait_group %0;" :: "n"(N0));
}

// ---------------- TF32 tensor-core GEMM: C = alpha*A*op(B) + bias -----------
// A: M x K (lda).  TRANSB: B is N x K (ldb) -> C=A*B^T.  else B is K x N (ldb).
// 128x128 tile, BK=16, 256 threads (8 warps, 2x4), warp tile 64x32,
// mma.sync.m16n8k8 tf32; fp32 staged via cp.async, cvt.rna.tf32 applied at
// fragment load (precision-critical for the Viterbi argmax consumer).
// SMEM: As[m][k] stride 20; Bs: TRANSB -> [n][k] stride 20, else [k][n] stride 136.
template<bool TRANSB, bool RELU>
__global__ __launch_bounds__(256, 2)
void tgemm(const float* __restrict__ A, const float* __restrict__ Bp,
           float* __restrict__ C, const float* __restrict__ bias,
           int M, int N, int K, int lda, int ldb, int ldc, float alpha,
           int HH, int sab, int sah, int sbb, int sbh, int scb, int sch)
{
    constexpr int BK    = 16;
    constexpr int ASTR  = 20;    // As row stride (floats): [m][k]
    constexpr int BSTRT = 20;    // Bs stride for TRANSB:  [n][k]
    constexpr int BSTRN = 136;   // Bs stride for non-trans: [k][n]

    int z = blockIdx.z;
    A  += (size_t)(z / HH) * sab + (size_t)(z % HH) * sah;
    Bp += (size_t)(z / HH) * sbb + (size_t)(z % HH) * sbh;
    C  += (size_t)(z / HH) * scb + (size_t)(z % HH) * sch;

    __shared__ unsigned As[2][128 * ASTR];
    __shared__ unsigned Bs[2][128 * ASTR];   // 2560 words: covers both layouts

    const int tid  = threadIdx.x;
    const int warp = tid >> 5;
    const int lane = tid & 31;
    const int qid  = lane >> 2;     // 0..7
    const int cid  = lane & 3;      // 0..3

    const int m0 = blockIdx.y * 128;
    const int n0 = blockIdx.x * 128;
    const int wm = (warp >> 2) * 64;   // warp m offset (0,64)
    const int wn = (warp & 3) * 32;    // warp n offset (0,32,64,96)

    // loaders
    const int arow = tid >> 1;          // 0..127
    const int ak   = (tid & 1) * 8;     // 0 or 8
    const int bkk  = tid >> 4;          // 0..15
    const int bnn  = (tid & 15) * 8;    // 0..120

    float acc[4][4][4];
#pragma unroll
    for (int i = 0; i < 4; i++)
#pragma unroll
        for (int j = 0; j < 4; j++)
#pragma unroll
            for (int r = 0; r < 4; r++) acc[i][j][r] = 0.f;

    const int nt = K / BK;

    // smem byte addresses for cp.async destinations
    const unsigned as_d0 = (unsigned)__cvta_generic_to_shared(&As[0][arow * ASTR + ak]);
    const unsigned as_d1 = (unsigned)__cvta_generic_to_shared(&As[1][arow * ASTR + ak]);
    unsigned bs_d0, bs_d1;
    if (TRANSB) {
        bs_d0 = (unsigned)__cvta_generic_to_shared(&Bs[0][arow * BSTRT + ak]);
        bs_d1 = (unsigned)__cvta_generic_to_shared(&Bs[1][arow * BSTRT + ak]);
    } else {
        bs_d0 = (unsigned)__cvta_generic_to_shared(&Bs[0][bkk * BSTRN + bnn]);
        bs_d1 = (unsigned)__cvta_generic_to_shared(&Bs[1][bkk * BSTRN + bnn]);
    }
    const bool bval = TRANSB ? (n0 + arow < N) : (n0 + bnn < N);

#define LOADG(k0, buf)                                                         \
    {                                                                          \
        const float* Ap = A + (size_t)(m0 + arow) * lda + (k0) + ak;           \
        unsigned ad = (buf) ? as_d1 : as_d0;                                   \
        cp16(ad,      Ap,     true);                                           \
        cp16(ad + 16, Ap + 4, true);                                           \
        unsigned bd = (buf) ? bs_d1 : bs_d0;                                   \
        if (TRANSB) {                                                          \
            const float* Bq = Bp + (size_t)(n0 + arow) * ldb + (k0) + ak;      \
            cp16(bd,      Bq,     bval);                                       \
            cp16(bd + 16, Bq + 4, bval);                                       \
        } else {                                                               \
            const float* Bq = Bp + (size_t)((k0) + bkk) * ldb + n0 + bnn;      \
            cp16(bd,      Bq,     bval);                                       \
            cp16(bd + 16, Bq + 4, bval);                                       \
        }                                                                      \
    }

    LOADG(0, 0);
    cp_commit();

    for (int t = 0; t < nt; t++) {
        const int cur = t & 1;
        if (t + 1 < nt) LOADG((t + 1) * BK, cur ^ 1);
        cp_commit();                 // always commit: keeps group accounting uniform
        cp_wait<1>();                // tile t has arrived (this thread)
        __syncthreads();             // tile t visible to all; all done computing t-1

        const unsigned* Ab = As[cur];
        const unsigned* Bb = Bs[cur];
#pragma unroll
        for (int ks = 0; ks < 2; ks++) {
            const int k0 = ks * 8;
            unsigned af[4][4], bf[4][2];
#pragma unroll
            for (int mt = 0; mt < 4; mt++) {
                const int rb = wm + mt * 16 + qid;
                af[mt][0] = f2tf(Ab[(rb    ) * ASTR + k0 + cid]);
                af[mt][1] = f2tf(Ab[(rb + 8) * ASTR + k0 + cid]);
                af[mt][2] = f2tf(Ab[(rb    ) * ASTR + k0 + cid + 4]);
                af[mt][3] = f2tf(Ab[(rb + 8) * ASTR + k0 + cid + 4]);
            }
#pragma unroll
            for (int ntl = 0; ntl < 4; ntl++) {
                const int nb = wn + ntl * 8 + qid;
                if (TRANSB) {
                    bf[ntl][0] = f2tf(Bb[nb * BSTRT + k0 + cid]);
                    bf[ntl][1] = f2tf(Bb[nb * BSTRT + k0 + cid + 4]);
                } else {
                    bf[ntl][0] = f2tf(Bb[(k0 + cid    ) * BSTRN + nb]);
                    bf[ntl][1] = f2tf(Bb[(k0 + cid + 4) * BSTRN + nb]);
                }
            }
#pragma unroll
            for (int mt = 0; mt < 4; mt++)
#pragma unroll
                for (int ntl = 0; ntl < 4; ntl++)
                    mma_tf32(acc[mt][ntl], af[mt], bf[ntl]);
        }
        __syncthreads();             // compute t done everywhere before buffer reuse
    }

    // ---- epilogue
#pragma unroll
    for (int mt = 0; mt < 4; mt++) {
        const int r0 = m0 + wm + mt * 16 + qid;
#pragma unroll
        for (int ntl = 0; ntl < 4; ntl++) {
            const int c0 = n0 + wn + ntl * 8 + cid * 2;
            float* d = acc[mt][ntl];
#pragma unroll
            for (int half = 0; half < 2; half++) {
                const int r = r0 + half * 8;
#pragma unroll
                for (int e = 0; e < 2; e++) {
                    const int n = c0 + e;
                    if (n < N) {
                        float v = d[half * 2 + e] * alpha;
                        if (bias) v += bias[n];
                        if (RELU) v = fmaxf(v, 0.f);
                        C[(size_t)r * ldc + n] = v;
                    }
                }
            }
        }
    }
#undef LOADG
}

// ---------------- row softmax (in place), rows of length 512 ----------------
__global__ void softmax_rows(float* __restrict__ p, int rows, int n)
{
    int row = blockIdx.x * blockDim.y + threadIdx.y;
    if (row >= rows) return;
    float* d = p + (size_t)row * n;
    int lane = threadIdx.x;

    float m = -INFINITY;
    for (int i = lane; i < n; i += 32) m = fmaxf(m, d[i]);
#pragma unroll
    for (int o = 16; o > 0; o >>= 1) m = fmaxf(m, __shfl_xor_sync(0xffffffffu, m, o));

    float s = 0.f;
    for (int i = lane; i < n; i += 32) s += __expf(d[i] - m);
#pragma unroll
    for (int o = 16; o > 0; o >>= 1) s += __shfl_xor_sync(0xffffffffu, s, o);

    float inv = 1.f / s;
    for (int i = lane; i < n; i += 32) d[i] = __expf(d[i] - m) * inv;
}

// ---------------- CRF: normalizer + numerator (warp0), viterbi (warp1) ------
__global__ __launch_bounds__(64)
void crf_kernel(const float* __restrict__ em, const int* __restrict__ labels,
                const unsigned char* __restrict__ mask,
                const float* __restrict__ start_t, const float* __restrict__ end_t,
                const float* __restrict__ trans,
                float* __restrict__ out,
                float* __restrict__ num, float* __restrict__ den,
                float* __restrict__ msum)
{
    using namespace cfg;
    const int b = blockIdx.x;
    const int warp = threadIdx.x >> 5;
    const int lane = threadIdx.x & 31;
    const int j = lane < T ? lane : T - 1;

    __shared__ unsigned char hist[S - 1][T];
    __shared__ unsigned char path[S];

    float tc[T];
#pragma unroll
    for (int i = 0; i < T; i++) tc[i] = trans[i * T + j];

    const float* emb = em + (size_t)b * S * T;

    if (warp == 0) {
        float sc = start_t[j] + emb[j];
        for (int s = 1; s < S; s++) {
            float v[T];
#pragma unroll
            for (int i = 0; i < T; i++)
                v[i] = __shfl_sync(0xffffffffu, sc, i) + tc[i];
            float m = v[0];
#pragma unroll
            for (int i = 1; i < T; i++) m = fmaxf(m, v[i]);
            float sum = 0.f;
#pragma unroll
            for (int i = 0; i < T; i++) sum += __expf(v[i] - m);
            float nxt = m + __logf(sum) + emb[s * T + j];
            float mf = mask[b * S + s] ? 1.f : 0.f;
            sc = mf > 0.f ? nxt : sc;
        }
        float x = (lane < T) ? sc + end_t[j] : -INFINITY;
        float m = x;
#pragma unroll
        for (int o = 16; o > 0; o >>= 1) m = fmaxf(m, __shfl_xor_sync(0xffffffffu, m, o));
        float sum = (lane < T) ? __expf(x - m) : 0.f;
#pragma unroll
        for (int o = 16; o > 0; o >>= 1) sum += __shfl_xor_sync(0xffffffffu, sum, o);
        float d = m + __logf(sum);

        float part = 0.f, ms = 0.f;
        for (int s = lane; s < S; s += 32) ms += mask[b * S + s] ? 1.f : 0.f;
        for (int s = 1 + lane; s < S; s += 32) {
            int lp = labels[b * S + s - 1];
            int lc = labels[b * S + s];
            float mf = mask[b * S + s] ? 1.f : 0.f;
            part += (trans[lp * T + lc] + emb[s * T + lc]) * mf;
        }
#pragma unroll
        for (int o = 16; o > 0; o >>= 1) {
            part += __shfl_xor_sync(0xffffffffu, part, o);
            ms   += __shfl_xor_sync(0xffffffffu, ms, o);
        }
        if (lane == 0) {
            int se = (int)ms - 1;
            int l0 = labels[b * S + 0];
            int lt = labels[b * S + se];
            num[b]  = start_t[l0] + emb[l0] + part + end_t[lt];
            den[b]  = d;
            msum[b] = ms;
        }
    } else {
        float sc = start_t[j] + emb[j];
        for (int s = 1; s < S; s++) {
            float best = -INFINITY;
            int bi = 0;
#pragma unroll
            for (int i = 0; i < T; i++) {
                float vi = __shfl_sync(0xffffffffu, sc, i) + tc[i];
                if (vi > best) { best = vi; bi = i; }
            }
            if (lane < T) hist[s - 1][j] = (unsigned char)bi;
            sc = best + emb[s * T + j];
        }
        float x = (lane < T) ? sc + end_t[j] : -INFINITY;
        int idx = lane;
#pragma unroll
        for (int o = 16; o > 0; o >>= 1) {
            float ov = __shfl_down_sync(0xffffffffu, x, o);
            int   oi = __shfl_down_sync(0xffffffffu, idx, o);
            if (ov > x || (ov == x && oi < idx)) { x = ov; idx = oi; }
        }
        idx = __shfl_sync(0xffffffffu, idx, 0);
        __syncwarp();
        if (lane == 0) {
            int cur = idx;
            path[S - 1] = (unsigned char)cur;
            for (int s = S - 1; s >= 1; s--) {
                cur = hist[s - 1][cur];
                path[s - 1] = (unsigned char)cur;
            }
        }
        __syncwarp();
        for (int s = lane; s < S; s += 32)
            out[b * S + s] = (float)path[s];
    }
}

// ---------------- final scalar: -llh ----------------------------------------
__global__ void llh_kernel(const float* __restrict__ num, const float* __restrict__ den,
                           const float* __restrict__ msum, float* __restrict__ out)
{
    using namespace cfg;
    int lane = threadIdx.x;
    float v = (lane < B) ? num[lane] - den[lane] : 0.f;
    float m = (lane < B) ? msum[lane] : 0.f;
#pragma unroll
    for (int o = 16; o > 0; o >>= 1) {
        v += __shfl_xor_sync(0xffffffffu, v, o);
        m += __shfl_xor_sync(0xffffffffu, m, o);
    }
    if (lane == 0) out[3 * BS] = -(v / m);
}

// ---------------- seg head: log_softmax(dec @ ent_w^T + ent_b) --------------
__global__ __launch_bounds__(256)
void seg_kernel(const float* __restrict__ dec, const float* __restrict__ ent_w,
                const float* __restrict__ ent_b, float* __restrict__ out)
{
    using namespace cfg;
    int warp = threadIdx.x >> 5;
    int lane = threadIdx.x & 31;
    int row = blockIdx.x * 8 + warp;
    if (row >= BS) return;
    const float* d = dec + (size_t)row * E;

    float a0 = 0.f, a1 = 0.f;
    for (int k = lane * 4; k < E; k += 128) {
        float4 dv = *(const float4*)(d + k);
        float4 w0 = *(const float4*)(ent_w + k);
        float4 w1 = *(const float4*)(ent_w + E + k);
        a0 += dv.x * w0.x + dv.y * w0.y + dv.z * w0.z + dv.w * w0.w;
        a1 += dv.x * w1.x + dv.y * w1.y + dv.z * w1.z + dv.w * w1.w;
    }
#pragma unroll
    for (int o = 16; o > 0; o >>= 1) {
        a0 += __shfl_xor_sync(0xffffffffu, a0, o);
        a1 += __shfl_xor_sync(0xffffffffu, a1, o);
    }
    if (lane == 0) {
        float z0 = a0 + ent_b[0];
        float z1 = a1 + ent_b[1];
        float m = fmaxf(z0, z1);
        float lse = m + __logf(__expf(z0 - m) + __expf(z1 - m));
        out[BS + (size_t)row * 2 + 0] = z0 - lse;
        out[BS + (size_t)row * 2 + 1] = z1 - lse;
    }
}

// ---------------- host launch ------------------------------------------------
extern "C" void kernel_launch(void* const* d_in, const int* in_sizes, int n_in,
                              void* d_out, int out_size)
{
    using namespace cfg;
    const float* x       = (const float*)d_in[0];
    const int*   labels  = (const int*)d_in[1];
    const unsigned char* mask = (const unsigned char*)d_in[2];
    const float* Win     = (const float*)d_in[3];
    const float* bin     = (const float*)d_in[4];
    const float* Wout    = (const float*)d_in[5];
    const float* bout    = (const float*)d_in[6];
    const float* crf_w   = (const float*)d_in[7];
    const float* crf_b   = (const float*)d_in[8];
    const float* start_t = (const float*)d_in[9];
    const float* end_t   = (const float*)d_in[10];
    const float* trans   = (const float*)d_in[11];
    const float* ent_w   = (const float*)d_in[12];
    const float* ent_b   = (const float*)d_in[13];
    float* out = (float*)d_out;

    float *qkv, *scores, *attn, *dec, *em, *num, *den, *msum;
    cudaGetSymbolAddress((void**)&qkv,    g_qkv);
    cudaGetSymbolAddress((void**)&scores, g_scores);
    cudaGetSymbolAddress((void**)&attn,   g_attn);
    cudaGetSymbolAddress((void**)&dec,    g_dec);
    cudaGetSymbolAddress((void**)&em,     g_em);
    cudaGetSymbolAddress((void**)&num,    g_num);
    cudaGetSymbolAddress((void**)&den,    g_den);
    cudaGetSymbolAddress((void**)&msum,   g_msum);

    // 1) qkv = x @ Win^T + bin          (16384 x 1536 x 512)
    tgemm<true, false><<<dim3(12, 128, 1), 256>>>(
        x, Win, qkv, bin, BS, 3 * E, E, E, E, 3 * E, 1.f,
        1, 0, 0, 0, 0, 0, 0);

    // 2) scores[b,h] = Q K^T / 16       (batched 64: 512 x 512 x 256)
    tgemm<true, false><<<dim3(4, 4, 64), 256>>>(
        qkv, qkv + E, scores, nullptr, S, S, HD, 3 * E, 3 * E, S, 1.f / 16.f,
        H, S * 3 * E, HD, S * 3 * E, HD, H * S * S, S * S);

    // 3) softmax over k
    softmax_rows<<<(B * H * S) / 8, dim3(32, 8)>>>(scores, B * H * S, S);

    // 4) attn[b,:,h*hd+] = P @ V        (batched 64: 512 x 256 x 512)
    tgemm<false, false><<<dim3(2, 4, 64), 256>>>(
        scores, qkv + 2 * E, attn, nullptr, S, HD, S, S, 3 * E, E, 1.f,
        H, H * S * S, S * S, S * 3 * E, HD, S * E, HD);

    // 5) dec = relu(attn @ Wout^T + bout)   (16384 x 512 x 512)
    tgemm<true, true><<<dim3(4, 128, 1), 256>>>(
        attn, Wout, dec, bout, BS, E, E, E, E, E, 1.f,
        1, 0, 0, 0, 0, 0, 0);

    // 6) em = dec @ crf_w^T + crf_b    (16384 x 24 x 512)
    tgemm<true, false><<<dim3(1, 128, 1), 256>>>(
        dec, crf_w, em, crf_b, BS, T, E, E, E, T, 1.f,
        1, 0, 0, 0, 0, 0, 0);

    // 7) CRF
    crf_kernel<<<B, 64>>>(em, labels, mask, start_t, end_t, trans,
                          out, num, den, msum);

    // 8) scalar loss
    llh_kernel<<<1, 32>>>(num, den, msum, out);

    // 9) seg head
    seg_kernel<<<BS / 8, 256>>>(dec, ent_w, ent_b, out);
}